// round 10
// baseline (speedup 1.0000x reference)
#include <cuda_runtime.h>
#include <cuda_bf16.h>
#include <cstdint>

// ---------------- problem constants ----------------
#define B_      4
#define CIN     256
#define COUT    128
#define HLO     64
#define WLO     64
#define PLO     (HLO*WLO)      // 4096
#define CRED    32
#define GROUPS  8
#define GC_     16
#define KK      25
#define SPAN    (KK*GROUPS)    // 200
#define HF      128
#define WF      128

// ---------------- scratch ----------------
__device__ float g_h0 [B_ * COUT * PLO];   // 8.4 MB
__device__ float g_wgt[B_ * SPAN * PLO];   // 13.1 MB

// ---------------- packed f32x2 helpers ----------------
__device__ __forceinline__ unsigned long long fma2(unsigned long long a,
                                                   unsigned long long b,
                                                   unsigned long long c) {
    unsigned long long d;
    asm("fma.rn.f32x2 %0, %1, %2, %3;" : "=l"(d) : "l"(a), "l"(b), "l"(c));
    return d;
}
__device__ __forceinline__ unsigned long long pack2(float v) {
    unsigned long long d;
    asm("mov.b64 %0, {%1, %1};" : "=l"(d) : "f"(v), "f"(v));
    return d;
}
union F2U { unsigned long long u; float2 f; };

// =====================================================================
// K1: h0 = W1x1 @ X per batch.
// Tile 128co x 64px, 256 threads, per-thread 8co x 4px.
// Grid 64 px-tiles x 4 batch = 256 CTAs -> 2 CTAs/SM resident
// (occ ~3.5 warps/SMSP). Ping-pong smem: ONE barrier per k-tile.
// =====================================================================
__global__ __launch_bounds__(256, 2)
void k1_conv1x1(const float* __restrict__ x,
                const float* __restrict__ w,
                const float* __restrict__ bias) {
    __shared__ float Xs[2][8][64];
    __shared__ unsigned long long Ws2[2][8][129];  // pad 129: row q vs q+4 -> 8 banks apart

    const int bb = blockIdx.y;
    const int p0 = blockIdx.x * 64;
    const int t  = threadIdx.x;
    const int ty = t >> 4;              // 0..15 -> 8 co each (ty + 16*i)
    const int tx = t & 15;              // 0..15 -> 4 px each (2*tx + 32*j, j<2)

    unsigned long long acc[8][2];
#pragma unroll
    for (int i = 0; i < 8; i++) {
        acc[i][0] = 0ull; acc[i][1] = 0ull;
    }

    const float* xb = x + (size_t)bb * CIN * PLO + p0;

    // load slices: X = 1 float2/thread (8 rows x 64 px = 512 floats),
    //              W = 1 float4/thread (128 co x 8 k)
    const int xrow = t >> 5;            // 0..7
    const int xcol = (t & 31) * 2;      // 0..62
    const int wco  = t >> 1;            // 0..127
    const int wk4  = (t & 1) * 4;       // 0 or 4

    float2 xv = *(const float2*)(xb + (size_t)xrow * PLO + xcol);
    float4 wv = *(const float4*)(w + wco * CIN + wk4);

    int p = 0;
    for (int k0 = 0; k0 < CIN; k0 += 8) {
        // stage current k-tile into buffer p
        *(float2*)&Xs[p][xrow][xcol] = xv;
        Ws2[p][wk4 + 0][wco] = pack2(wv.x);
        Ws2[p][wk4 + 1][wco] = pack2(wv.y);
        Ws2[p][wk4 + 2][wco] = pack2(wv.z);
        Ws2[p][wk4 + 3][wco] = pack2(wv.w);
        __syncthreads();                 // single barrier per iteration

        if (k0 + 8 < CIN) {              // prefetch next tile (overlaps compute)
            xv = *(const float2*)(xb + (size_t)(k0 + 8 + xrow) * PLO + xcol);
            wv = *(const float4*)(w + wco * CIN + k0 + 8 + wk4);
        }

#pragma unroll
        for (int kk = 0; kk < 8; kk++) {
            unsigned long long wp[8], xr[2];
#pragma unroll
            for (int i = 0; i < 8; i++) wp[i] = Ws2[p][kk][ty + 16 * i];
            xr[0] = *(const unsigned long long*)&Xs[p][kk][2 * tx];
            xr[1] = *(const unsigned long long*)&Xs[p][kk][2 * tx + 32];
#pragma unroll
            for (int i = 0; i < 8; i++) {
                acc[i][0] = fma2(wp[i], xr[0], acc[i][0]);
                acc[i][1] = fma2(wp[i], xr[1], acc[i][1]);
            }
        }
        p ^= 1;                          // next iter writes the other buffer
    }

#pragma unroll
    for (int i = 0; i < 8; i++) {
        int co = ty + 16 * i;
        float bv = bias[co];
        float* op = g_h0 + ((size_t)bb * COUT + co) * PLO + p0;
#pragma unroll
        for (int j = 0; j < 2; j++) {
            F2U v; v.u = acc[i][j];
            *(float2*)&op[2 * tx + 32 * j] = make_float2(v.f.x + bv, v.f.y + bv);
        }
    }
}

// =====================================================================
// K2: kernel-gen at 64x64 (R3-measured version, 256 threads).
// =====================================================================
__global__ __launch_bounds__(256, 1)
void k2_kernelgen(const float* __restrict__ w_red,  const float* __restrict__ b_red,
                  const float* __restrict__ gamma,  const float* __restrict__ beta,
                  const float* __restrict__ mean,   const float* __restrict__ var,
                  const float* __restrict__ w_span, const float* __restrict__ b_span) {
    __shared__ float Hs[32][128];
    __shared__ float Wrs[32][33];
    __shared__ float Rs[32][132];

    const int bb = blockIdx.y;
    const int p0 = blockIdx.x * 128;
    const int t  = threadIdx.x;
    const int ty = t >> 4;
    const int tx = t & 15;

    unsigned long long acc[2][4];
#pragma unroll
    for (int i = 0; i < 2; i++)
#pragma unroll
        for (int j = 0; j < 4; j++) acc[i][j] = 0ull;

    for (int k0 = 0; k0 < COUT; k0 += 32) {
#pragma unroll
        for (int q = 0; q < 4; q++) {
            int f   = t + 256 * q;
            int row = f >> 5;
            int c4  = (f & 31) * 4;
            float4 v = *(const float4*)(g_h0 + ((size_t)(bb * COUT + k0 + row)) * PLO + p0 + c4);
            *(float4*)&Hs[row][c4] = v;
        }
        {
            int cr  = t >> 3;
            int kk4 = (t & 7) * 4;
            float4 v = *(const float4*)(w_red + cr * COUT + k0 + kk4);
            Wrs[kk4 + 0][cr] = v.x; Wrs[kk4 + 1][cr] = v.y;
            Wrs[kk4 + 2][cr] = v.z; Wrs[kk4 + 3][cr] = v.w;
        }
        __syncthreads();
#pragma unroll
        for (int kk = 0; kk < 32; kk++) {
            unsigned long long wp0 = pack2(Wrs[kk][ty]);
            unsigned long long wp1 = pack2(Wrs[kk][ty + 16]);
#pragma unroll
            for (int j = 0; j < 4; j++) {
                unsigned long long xv = *(const unsigned long long*)&Hs[kk][2 * tx + 32 * j];
                acc[0][j] = fma2(wp0, xv, acc[0][j]);
                acc[1][j] = fma2(wp1, xv, acc[1][j]);
            }
        }
        __syncthreads();
    }

#pragma unroll
    for (int i = 0; i < 2; i++) {
        int cr = ty + 16 * i;
        float sc  = gamma[cr] * rsqrtf(var[cr] + 1e-5f);
        float off = (b_red[cr] - mean[cr]) * sc + beta[cr];
#pragma unroll
        for (int j = 0; j < 4; j++) {
            F2U v; v.u = acc[i][j];
            Rs[cr][2 * tx + 32 * j]     = fmaxf(v.f.x * sc + off, 0.f);
            Rs[cr][2 * tx + 32 * j + 1] = fmaxf(v.f.y * sc + off, 0.f);
        }
    }
    __syncthreads();

    if (t < SPAN) {
        const int co = t;
        unsigned long long wp[CRED];
        const float* wsp = w_span + co * CRED;
#pragma unroll
        for (int k = 0; k < CRED; k++) wp[k] = pack2(__ldg(wsp + k));
        const float bs = b_span[co];
        float* wout = g_wgt + ((size_t)bb * SPAN + co) * PLO + p0;

        for (int p4 = 0; p4 < 128; p4 += 4) {
            unsigned long long a0 = pack2(bs), a1 = pack2(bs);
#pragma unroll
            for (int k = 0; k < CRED; k++) {
                ulonglong2 rv = *(const ulonglong2*)&Rs[k][p4];
                a0 = fma2(wp[k], rv.x, a0);
                a1 = fma2(wp[k], rv.y, a1);
            }
            F2U u0, u1; u0.u = a0; u1.u = a1;
            *(float4*)&wout[p4] = make_float4(u0.f.x, u0.f.y, u1.f.x, u1.f.y);
        }
    }
}

// =====================================================================
// K3: involution (R3-measured version: plain fmaf, static smem, occ 2).
// =====================================================================
__global__ __launch_bounds__(256, 2)
void k3_involution(float* __restrict__ outp) {
    __shared__ float Hs[16 * 336];
    __shared__ float Wg[KK * 256];

    const int tile = blockIdx.x;
    const int g    = blockIdx.y;
    const int bb   = blockIdx.z;
    const int m0   = (tile >> 2) * 16;
    const int n0   = (tile & 3) * 16;
    const int t    = threadIdx.x;

    for (int idx = t; idx < 16 * 324; idx += 256) {
        int c  = idx / 324;
        int r2 = idx - c * 324;
        int mm = r2 / 18;
        int nn = r2 - mm * 18;
        int gm = m0 + mm - 1;
        int gn = n0 + nn - 1;
        float v = 0.f;
        if (gm >= 0 && gm < HLO && gn >= 0 && gn < WLO)
            v = g_h0[((size_t)(bb * COUT + g * GC_ + c)) * PLO + gm * WLO + gn];
        Hs[c * 336 + mm * 18 + nn] = v;
    }
    for (int idx = t; idx < KK * 256; idx += 256) {
        int k  = idx >> 8;
        int pp = idx & 255;
        int ml = pp >> 4;
        int nl = pp & 15;
        Wg[idx] = g_wgt[((size_t)(bb * SPAN + g * KK + k)) * PLO + (m0 + ml) * WLO + (n0 + nl)];
    }
    __syncthreads();

    const int c  = t >> 4;
    const int nl = t & 15;
    const int xg = (n0 + nl) * 2;

    for (int ml = 0; ml < 16; ml++) {
        float wv[KK];
#pragma unroll
        for (int k = 0; k < KK; k++) wv[k] = Wg[k * 256 + ml * 16 + nl];
        float hv[9];
#pragma unroll
        for (int dr = 0; dr < 3; dr++)
#pragma unroll
            for (int dc = 0; dc < 3; dc++)
                hv[dr * 3 + dc] = Hs[c * 336 + (ml + dr) * 18 + (nl + dc)];

        float a00 = 0.f, a01 = 0.f, a10 = 0.f, a11 = 0.f;
#pragma unroll
        for (int kh = 0; kh < 5; kh++) {
#pragma unroll
            for (int kw = 0; kw < 5; kw++) {
                const float w = wv[kh * 5 + kw];
                const int r0 = ((kh - 2) >> 1) + 1;
                const int r1 = ((kh - 1) >> 1) + 1;
                const int c0 = ((kw - 2) >> 1) + 1;
                const int c1 = ((kw - 1) >> 1) + 1;
                a00 = fmaf(w, hv[r0 * 3 + c0], a00);
                a01 = fmaf(w, hv[r0 * 3 + c1], a01);
                a10 = fmaf(w, hv[r1 * 3 + c0], a10);
                a11 = fmaf(w, hv[r1 * 3 + c1], a11);
            }
        }
        const int yb = (m0 + ml) * 2;
        size_t ob = ((size_t)(bb * COUT + g * GC_ + c) * HF + yb) * WF + xg;
        *(float2*)&outp[ob]      = make_float2(a00, a01);
        *(float2*)&outp[ob + WF] = make_float2(a10, a11);
    }
}

// =====================================================================
extern "C" void kernel_launch(void* const* d_in, const int* in_sizes, int n_in,
                              void* d_out, int out_size) {
    const float* x      = (const float*)d_in[0];
    const float* w1x1   = (const float*)d_in[1];
    const float* b1x1   = (const float*)d_in[2];
    const float* w_red  = (const float*)d_in[3];
    const float* b_red  = (const float*)d_in[4];
    const float* gamma  = (const float*)d_in[5];
    const float* beta   = (const float*)d_in[6];
    const float* mean   = (const float*)d_in[7];
    const float* var    = (const float*)d_in[8];
    const float* w_span = (const float*)d_in[9];
    const float* b_span = (const float*)d_in[10];
    float* out = (float*)d_out;

    k1_conv1x1 <<<dim3(PLO / 64, B_), 256>>>(x, w1x1, b1x1);
    k2_kernelgen<<<dim3(PLO / 128, B_), 256>>>(w_red, b_red, gamma, beta, mean, var,
                                               w_span, b_span);
    k3_involution<<<dim3(16, GROUPS, B_), 256>>>(out);
}

// round 12
// speedup vs baseline: 1.0856x; 1.0856x over previous
#include <cuda_runtime.h>
#include <cuda_bf16.h>
#include <cstdint>

// ---------------- problem constants ----------------
#define B_      4
#define CIN     256
#define COUT    128
#define HLO     64
#define WLO     64
#define PLO     (HLO*WLO)      // 4096
#define CRED    32
#define GROUPS  8
#define GC_     16
#define KK      25
#define SPAN    (KK*GROUPS)    // 200
#define HF      128
#define WF      128
#define H0N     (B_ * COUT * PLO)

// ---------------- scratch ----------------
__device__ float g_h0p[2][H0N];            // 16.8 MB : k-split partials
__device__ float g_wgt [B_ * SPAN * PLO];  // 13.1 MB

// ---------------- packed f32x2 helpers ----------------
__device__ __forceinline__ unsigned long long fma2(unsigned long long a,
                                                   unsigned long long b,
                                                   unsigned long long c) {
    unsigned long long d;
    asm("fma.rn.f32x2 %0, %1, %2, %3;" : "=l"(d) : "l"(a), "l"(b), "l"(c));
    return d;
}
__device__ __forceinline__ unsigned long long pack2(float v) {
    unsigned long long d;
    asm("mov.b64 %0, {%1, %1};" : "=l"(d) : "f"(v), "f"(v));
    return d;
}
union F2U { unsigned long long u; float2 f; };

// =====================================================================
// K1: partial h0 = W1x1[:, khalf] @ X[khalf] per batch.
// EXACT R8 geometry (tile 128co x 128px, 256 thr, 8co x 8px/thread,
// register double-buffer) but K split across 2 CTAs -> grid 256,
// 2 CTAs/SM resident -> 4 warps/SMSP.
// =====================================================================
__global__ __launch_bounds__(256, 2)
void k1_conv1x1(const float* __restrict__ x,
                const float* __restrict__ w,
                const float* __restrict__ bias) {
    __shared__ float Xs[8][128];
    __shared__ unsigned long long Ws2[8][128];

    const int p0 = blockIdx.x * 128;
    const int hf = blockIdx.y;          // k half: 0 or 1
    const int bb = blockIdx.z;
    const int kb = hf * 128;            // k base
    const int t  = threadIdx.x;
    const int ty = t >> 4;
    const int tx = t & 15;

    unsigned long long acc[8][4];
#pragma unroll
    for (int i = 0; i < 8; i++)
#pragma unroll
        for (int j = 0; j < 4; j++) acc[i][j] = 0ull;

    const float* xb = x + (size_t)bb * CIN * PLO + (size_t)kb * PLO + p0;
    const int xrow = t >> 5;
    const int xcol = (t & 31) * 4;
    const int wco  = t >> 1;
    const int wk4  = (t & 1) * 4;

    float4 xv = *(const float4*)(xb + (size_t)xrow * PLO + xcol);
    float4 wv = *(const float4*)(w + wco * CIN + kb + wk4);

    for (int k0 = 0; k0 < 128; k0 += 8) {
        *(float4*)&Xs[xrow][xcol] = xv;
        Ws2[wk4 + 0][wco] = pack2(wv.x);
        Ws2[wk4 + 1][wco] = pack2(wv.y);
        Ws2[wk4 + 2][wco] = pack2(wv.z);
        Ws2[wk4 + 3][wco] = pack2(wv.w);
        __syncthreads();

        if (k0 + 8 < 128) {
            xv = *(const float4*)(xb + (size_t)(k0 + 8 + xrow) * PLO + xcol);
            wv = *(const float4*)(w + wco * CIN + kb + k0 + 8 + wk4);
        }

#pragma unroll
        for (int kk = 0; kk < 8; kk++) {
            unsigned long long wp[8], xr[4];
#pragma unroll
            for (int i = 0; i < 8; i++) wp[i] = Ws2[kk][ty + 16 * i];
#pragma unroll
            for (int j = 0; j < 4; j++)
                xr[j] = *(const unsigned long long*)&Xs[kk][2 * tx + 32 * j];
#pragma unroll
            for (int i = 0; i < 8; i++)
#pragma unroll
                for (int j = 0; j < 4; j++)
                    acc[i][j] = fma2(wp[i], xr[j], acc[i][j]);
        }
        __syncthreads();
    }

#pragma unroll
    for (int i = 0; i < 8; i++) {
        int co = ty + 16 * i;
        float bv = (hf == 0) ? bias[co] : 0.f;   // bias once
        float* op = g_h0p[hf] + ((size_t)bb * COUT + co) * PLO + p0;
#pragma unroll
        for (int j = 0; j < 4; j++) {
            F2U v; v.u = acc[i][j];
            *(float2*)&op[2 * tx + 32 * j] = make_float2(v.f.x + bv, v.f.y + bv);
        }
    }
}

// =====================================================================
// K2: kernel-gen at 64x64 (measured version; H tile = sum of partials).
// =====================================================================
__global__ __launch_bounds__(256, 1)
void k2_kernelgen(const float* __restrict__ w_red,  const float* __restrict__ b_red,
                  const float* __restrict__ gamma,  const float* __restrict__ beta,
                  const float* __restrict__ mean,   const float* __restrict__ var,
                  const float* __restrict__ w_span, const float* __restrict__ b_span) {
    __shared__ float Hs[32][128];
    __shared__ float Wrs[32][33];
    __shared__ float Rs[32][132];

    const int bb = blockIdx.y;
    const int p0 = blockIdx.x * 128;
    const int t  = threadIdx.x;
    const int ty = t >> 4;
    const int tx = t & 15;

    unsigned long long acc[2][4];
#pragma unroll
    for (int i = 0; i < 2; i++)
#pragma unroll
        for (int j = 0; j < 4; j++) acc[i][j] = 0ull;

    for (int k0 = 0; k0 < COUT; k0 += 32) {
#pragma unroll
        for (int q = 0; q < 4; q++) {
            int f   = t + 256 * q;
            int row = f >> 5;
            int c4  = (f & 31) * 4;
            size_t off = ((size_t)(bb * COUT + k0 + row)) * PLO + p0 + c4;
            float4 a = *(const float4*)(g_h0p[0] + off);
            float4 b = *(const float4*)(g_h0p[1] + off);
            float4 v = make_float4(a.x + b.x, a.y + b.y, a.z + b.z, a.w + b.w);
            *(float4*)&Hs[row][c4] = v;
        }
        {
            int cr  = t >> 3;
            int kk4 = (t & 7) * 4;
            float4 v = *(const float4*)(w_red + cr * COUT + k0 + kk4);
            Wrs[kk4 + 0][cr] = v.x; Wrs[kk4 + 1][cr] = v.y;
            Wrs[kk4 + 2][cr] = v.z; Wrs[kk4 + 3][cr] = v.w;
        }
        __syncthreads();
#pragma unroll
        for (int kk = 0; kk < 32; kk++) {
            unsigned long long wp0 = pack2(Wrs[kk][ty]);
            unsigned long long wp1 = pack2(Wrs[kk][ty + 16]);
#pragma unroll
            for (int j = 0; j < 4; j++) {
                unsigned long long xv = *(const unsigned long long*)&Hs[kk][2 * tx + 32 * j];
                acc[0][j] = fma2(wp0, xv, acc[0][j]);
                acc[1][j] = fma2(wp1, xv, acc[1][j]);
            }
        }
        __syncthreads();
    }

#pragma unroll
    for (int i = 0; i < 2; i++) {
        int cr = ty + 16 * i;
        float sc  = gamma[cr] * rsqrtf(var[cr] + 1e-5f);
        float off = (b_red[cr] - mean[cr]) * sc + beta[cr];
#pragma unroll
        for (int j = 0; j < 4; j++) {
            F2U v; v.u = acc[i][j];
            Rs[cr][2 * tx + 32 * j]     = fmaxf(v.f.x * sc + off, 0.f);
            Rs[cr][2 * tx + 32 * j + 1] = fmaxf(v.f.y * sc + off, 0.f);
        }
    }
    __syncthreads();

    if (t < SPAN) {
        const int co = t;
        unsigned long long wp[CRED];
        const float* wsp = w_span + co * CRED;
#pragma unroll
        for (int k = 0; k < CRED; k++) wp[k] = pack2(__ldg(wsp + k));
        const float bs = b_span[co];
        float* wout = g_wgt + ((size_t)bb * SPAN + co) * PLO + p0;

        for (int p4 = 0; p4 < 128; p4 += 4) {
            unsigned long long a0 = pack2(bs), a1 = pack2(bs);
#pragma unroll
            for (int k = 0; k < CRED; k++) {
                ulonglong2 rv = *(const ulonglong2*)&Rs[k][p4];
                a0 = fma2(wp[k], rv.x, a0);
                a1 = fma2(wp[k], rv.y, a1);
            }
            F2U u0, u1; u0.u = a0; u1.u = a1;
            *(float4*)&wout[p4] = make_float4(u0.f.x, u0.f.y, u1.f.x, u1.f.y);
        }
    }
}

// =====================================================================
// K3: involution (measured version; h0 = sum of partials at load).
// =====================================================================
__global__ __launch_bounds__(256, 2)
void k3_involution(float* __restrict__ outp) {
    __shared__ float Hs[16 * 336];
    __shared__ float Wg[KK * 256];

    const int tile = blockIdx.x;
    const int g    = blockIdx.y;
    const int bb   = blockIdx.z;
    const int m0   = (tile >> 2) * 16;
    const int n0   = (tile & 3) * 16;
    const int t    = threadIdx.x;

    for (int idx = t; idx < 16 * 324; idx += 256) {
        int c  = idx / 324;
        int r2 = idx - c * 324;
        int mm = r2 / 18;
        int nn = r2 - mm * 18;
        int gm = m0 + mm - 1;
        int gn = n0 + nn - 1;
        float v = 0.f;
        if (gm >= 0 && gm < HLO && gn >= 0 && gn < WLO) {
            size_t off = ((size_t)(bb * COUT + g * GC_ + c)) * PLO + gm * WLO + gn;
            v = g_h0p[0][off] + g_h0p[1][off];
        }
        Hs[c * 336 + mm * 18 + nn] = v;
    }
    for (int idx = t; idx < KK * 256; idx += 256) {
        int k  = idx >> 8;
        int pp = idx & 255;
        int ml = pp >> 4;
        int nl = pp & 15;
        Wg[idx] = g_wgt[((size_t)(bb * SPAN + g * KK + k)) * PLO + (m0 + ml) * WLO + (n0 + nl)];
    }
    __syncthreads();

    const int c  = t >> 4;
    const int nl = t & 15;
    const int xg = (n0 + nl) * 2;

    for (int ml = 0; ml < 16; ml++) {
        float wv[KK];
#pragma unroll
        for (int k = 0; k < KK; k++) wv[k] = Wg[k * 256 + ml * 16 + nl];
        float hv[9];
#pragma unroll
        for (int dr = 0; dr < 3; dr++)
#pragma unroll
            for (int dc = 0; dc < 3; dc++)
                hv[dr * 3 + dc] = Hs[c * 336 + (ml + dr) * 18 + (nl + dc)];

        float a00 = 0.f, a01 = 0.f, a10 = 0.f, a11 = 0.f;
#pragma unroll
        for (int kh = 0; kh < 5; kh++) {
#pragma unroll
            for (int kw = 0; kw < 5; kw++) {
                const float w = wv[kh * 5 + kw];
                const int r0 = ((kh - 2) >> 1) + 1;
                const int r1 = ((kh - 1) >> 1) + 1;
                const int c0 = ((kw - 2) >> 1) + 1;
                const int c1 = ((kw - 1) >> 1) + 1;
                a00 = fmaf(w, hv[r0 * 3 + c0], a00);
                a01 = fmaf(w, hv[r0 * 3 + c1], a01);
                a10 = fmaf(w, hv[r1 * 3 + c0], a10);
                a11 = fmaf(w, hv[r1 * 3 + c1], a11);
            }
        }
        const int yb = (m0 + ml) * 2;
        size_t ob = ((size_t)(bb * COUT + g * GC_ + c) * HF + yb) * WF + xg;
        *(float2*)&outp[ob]      = make_float2(a00, a01);
        *(float2*)&outp[ob + WF] = make_float2(a10, a11);
    }
}

// =====================================================================
extern "C" void kernel_launch(void* const* d_in, const int* in_sizes, int n_in,
                              void* d_out, int out_size) {
    const float* x      = (const float*)d_in[0];
    const float* w1x1   = (const float*)d_in[1];
    const float* b1x1   = (const float*)d_in[2];
    const float* w_red  = (const float*)d_in[3];
    const float* b_red  = (const float*)d_in[4];
    const float* gamma  = (const float*)d_in[5];
    const float* beta   = (const float*)d_in[6];
    const float* mean   = (const float*)d_in[7];
    const float* var    = (const float*)d_in[8];
    const float* w_span = (const float*)d_in[9];
    const float* b_span = (const float*)d_in[10];
    float* out = (float*)d_out;

    k1_conv1x1 <<<dim3(PLO / 128, 2, B_), 256>>>(x, w1x1, b1x1);
    k2_kernelgen<<<dim3(PLO / 128, B_), 256>>>(w_red, b_red, gamma, beta, mean, var,
                                               w_span, b_span);
    k3_involution<<<dim3(16, GROUPS, B_), 256>>>(out);
}

// round 17
// speedup vs baseline: 1.1449x; 1.0547x over previous
#include <cuda_runtime.h>
#include <cuda_bf16.h>
#include <cstdint>

// ---------------- problem constants ----------------
#define B_      4
#define CIN     256
#define COUT    128
#define HLO     64
#define WLO     64
#define PLO     (HLO*WLO)      // 4096
#define CRED    32
#define GROUPS  8
#define GC_     16
#define KK      25
#define SPAN    (KK*GROUPS)    // 200
#define HF      128
#define WF      128

// ---------------- scratch ----------------
__device__ float    g_h0 [B_ * COUT * PLO];   // 8.4 MB
__device__ float    g_wgt[B_ * SPAN * PLO];   // 13.1 MB
__device__ unsigned g_w2hi[COUT * CIN / 2];   // W hi-split, bf16x2 (k even|odd)
__device__ unsigned g_w2lo[COUT * CIN / 2];   // W lo-split

// ---------------- packed f32x2 helpers (K2) ----------------
__device__ __forceinline__ unsigned long long fma2(unsigned long long a,
                                                   unsigned long long b,
                                                   unsigned long long c) {
    unsigned long long d;
    asm("fma.rn.f32x2 %0, %1, %2, %3;" : "=l"(d) : "l"(a), "l"(b), "l"(c));
    return d;
}
__device__ __forceinline__ unsigned long long pack2(float v) {
    unsigned long long d;
    asm("mov.b64 %0, {%1, %1};" : "=l"(d) : "f"(v), "f"(v));
    return d;
}
union F2U { unsigned long long u; float2 f; };

// ---------------- warp mma (sm_80+ PTX, valid on compute_103) ----------
__device__ __forceinline__ void mma_bf16(float* c, const uint4& a, const uint2& b) {
    asm volatile(
        "mma.sync.aligned.m16n8k16.row.col.f32.bf16.bf16.f32 "
        "{%0,%1,%2,%3}, {%4,%5,%6,%7}, {%8,%9}, {%0,%1,%2,%3};"
        : "+f"(c[0]), "+f"(c[1]), "+f"(c[2]), "+f"(c[3])
        : "r"(a.x), "r"(a.y), "r"(a.z), "r"(a.w), "r"(b.x), "r"(b.y));
}

// K1 smem layout: fragment-linear tiles.
// A tile (m16 x k16) = 32 lanes x 16B = 512B ; B tile (k16 x n8) = 32 x 8B = 256B
#define TN      64
#define SM_AHI  0
#define SM_ALO  65536
#define SM_BHI  131072
#define SM_BLO  163840
#define SM_TOT  196608

// =====================================================================
// K0: split W into bf16 hi/lo pairs (once per launch)
// =====================================================================
__global__ void k0_wsplit(const float* __restrict__ w) {
    int p = blockIdx.x * 256 + threadIdx.x;
    float a = w[2 * p], b = w[2 * p + 1];
    __nv_bfloat16 ah = __float2bfloat16(a), bh = __float2bfloat16(b);
    __nv_bfloat16 al = __float2bfloat16(a - __bfloat162float(ah));
    __nv_bfloat16 bl = __float2bfloat16(b - __bfloat162float(bh));
    g_w2hi[p] = (uint32_t)__bfloat16_as_ushort(ah) | ((uint32_t)__bfloat16_as_ushort(bh) << 16);
    g_w2lo[p] = (uint32_t)__bfloat16_as_ushort(al) | ((uint32_t)__bfloat16_as_ushort(bl) << 16);
}

// =====================================================================
// K1: h0 = W @ X via warp mma.sync bf16 2-split.
// CTA: M=128co x N=64px, K=256. 8 warps = 4(M) x 2(N); warp = 32co x 32px.
// D = Whi*Xhi + Whi*Xlo + Wlo*Xhi, fp32 accumulate.
// =====================================================================
__global__ __launch_bounds__(256)
void k1_mma(const float* __restrict__ x, const float* __restrict__ bias) {
    extern __shared__ char sm[];
    const int t    = threadIdx.x;
    const int wid  = t >> 5, lane = t & 31;
    const int p0   = blockIdx.x * TN;
    const int bb   = blockIdx.y;

    // ---- stage A (both splits) in fragment layout ----
    // a-frag m16n8k16: reg q bit0 -> row+8, bit1 -> col+8;
    // lane = (row%8)*4 + (col%8)/2
    for (int i = t; i < COUT * CIN / 2; i += 256) {
        int m  = i >> 7;            // 0..127
        int kp = i & 127;           // k pair, c = 2*kp
        uint32_t slot = (uint32_t)(((m >> 4) * 16 + (kp >> 3)) * 512)
                      + (uint32_t)(((m & 7) * 4 + (kp & 3)) * 16)
                      + (uint32_t)((((m >> 3) & 1) | (((kp >> 2) & 1) << 1)) * 4);
        *(uint32_t*)(sm + SM_AHI + slot) = g_w2hi[i];
        *(uint32_t*)(sm + SM_ALO + slot) = g_w2lo[i];
    }
    // ---- stage B: coalesced X read, split, scatter into fragment layout ----
    // b-frag: lane = (n%8)*4 + (k%8)/2 ; reg q = (k%16)/8 ; half = k&1
    const float* xb = x + (size_t)bb * CIN * PLO + p0;
    for (int i = t; i < CIN * TN; i += 256) {
        int k = i >> 6, n = i & 63;
        float v = xb[(size_t)k * PLO + n];
        __nv_bfloat16 h = __float2bfloat16(v);
        __nv_bfloat16 l = __float2bfloat16(v - __bfloat162float(h));
        uint32_t slot = (uint32_t)(((n >> 3) * 16 + (k >> 4)) * 256)
                      + (uint32_t)(((((n & 7) << 2) | ((k >> 1) & 3))) * 8)
                      + (uint32_t)(((k >> 3) & 1) * 4)
                      + (uint32_t)((k & 1) * 2);
        *(__nv_bfloat16*)(sm + SM_BHI + slot) = h;
        *(__nv_bfloat16*)(sm + SM_BLO + slot) = l;
    }
    __syncthreads();

    // ---- compute ----
    const int wm = wid >> 1;        // 0..3 -> m tiles {2wm, 2wm+1}
    const int wn = wid & 1;         // 0..1 -> n tiles {4wn..4wn+3}
    float acc[2][4][4];
#pragma unroll
    for (int i = 0; i < 2; i++)
#pragma unroll
        for (int j = 0; j < 4; j++)
#pragma unroll
            for (int q = 0; q < 4; q++) acc[i][j][q] = 0.f;

    for (int kt = 0; kt < 16; kt++) {
        uint4 ahi[2], alo[2];
#pragma unroll
        for (int i = 0; i < 2; i++) {
            uint32_t base = (uint32_t)(((wm * 2 + i) * 16 + kt) * 512 + lane * 16);
            ahi[i] = *(const uint4*)(sm + SM_AHI + base);
            alo[i] = *(const uint4*)(sm + SM_ALO + base);
        }
        uint2 bhi[4], blo[4];
#pragma unroll
        for (int j = 0; j < 4; j++) {
            uint32_t base = (uint32_t)(((wn * 4 + j) * 16 + kt) * 256 + lane * 8);
            bhi[j] = *(const uint2*)(sm + SM_BHI + base);
            blo[j] = *(const uint2*)(sm + SM_BLO + base);
        }
#pragma unroll
        for (int i = 0; i < 2; i++)
#pragma unroll
            for (int j = 0; j < 4; j++) {
                mma_bf16(acc[i][j], ahi[i], bhi[j]);
                mma_bf16(acc[i][j], ahi[i], blo[j]);
                mma_bf16(acc[i][j], alo[i], bhi[j]);
            }
    }

    // ---- epilogue: d-frag rows lane/4 (+8), cols (lane%4)*2 (+1) ----
#pragma unroll
    for (int i = 0; i < 2; i++) {
        int mb = (wm * 2 + i) * 16 + (lane >> 2);
        float bv0 = bias[mb], bv1 = bias[mb + 8];
        float* r0 = g_h0 + ((size_t)bb * COUT + mb)     * PLO + p0;
        float* r1 = g_h0 + ((size_t)bb * COUT + mb + 8) * PLO + p0;
#pragma unroll
        for (int j = 0; j < 4; j++) {
            int n = (wn * 4 + j) * 8 + (lane & 3) * 2;
            *(float2*)&r0[n] = make_float2(acc[i][j][0] + bv0, acc[i][j][1] + bv0);
            *(float2*)&r1[n] = make_float2(acc[i][j][2] + bv1, acc[i][j][3] + bv1);
        }
    }
}

// =====================================================================
// K2: kernel-gen at 64x64 (measured R3 version).
// =====================================================================
__global__ __launch_bounds__(256, 1)
void k2_kernelgen(const float* __restrict__ w_red,  const float* __restrict__ b_red,
                  const float* __restrict__ gamma,  const float* __restrict__ beta,
                  const float* __restrict__ mean,   const float* __restrict__ var,
                  const float* __restrict__ w_span, const float* __restrict__ b_span) {
    __shared__ float Hs[32][128];
    __shared__ float Wrs[32][33];
    __shared__ float Rs[32][132];

    const int bb = blockIdx.y;
    const int p0 = blockIdx.x * 128;
    const int t  = threadIdx.x;
    const int ty = t >> 4;
    const int tx = t & 15;

    unsigned long long acc[2][4];
#pragma unroll
    for (int i = 0; i < 2; i++)
#pragma unroll
        for (int j = 0; j < 4; j++) acc[i][j] = 0ull;

    for (int k0 = 0; k0 < COUT; k0 += 32) {
#pragma unroll
        for (int q = 0; q < 4; q++) {
            int f   = t + 256 * q;
            int row = f >> 5;
            int c4  = (f & 31) * 4;
            float4 v = *(const float4*)(g_h0 + ((size_t)(bb * COUT + k0 + row)) * PLO + p0 + c4);
            *(float4*)&Hs[row][c4] = v;
        }
        {
            int cr  = t >> 3;
            int kk4 = (t & 7) * 4;
            float4 v = *(const float4*)(w_red + cr * COUT + k0 + kk4);
            Wrs[kk4 + 0][cr] = v.x; Wrs[kk4 + 1][cr] = v.y;
            Wrs[kk4 + 2][cr] = v.z; Wrs[kk4 + 3][cr] = v.w;
        }
        __syncthreads();
#pragma unroll
        for (int kk = 0; kk < 32; kk++) {
            unsigned long long wp0 = pack2(Wrs[kk][ty]);
            unsigned long long wp1 = pack2(Wrs[kk][ty + 16]);
#pragma unroll
            for (int j = 0; j < 4; j++) {
                unsigned long long xv = *(const unsigned long long*)&Hs[kk][2 * tx + 32 * j];
                acc[0][j] = fma2(wp0, xv, acc[0][j]);
                acc[1][j] = fma2(wp1, xv, acc[1][j]);
            }
        }
        __syncthreads();
    }

#pragma unroll
    for (int i = 0; i < 2; i++) {
        int cr = ty + 16 * i;
        float sc  = gamma[cr] * rsqrtf(var[cr] + 1e-5f);
        float off = (b_red[cr] - mean[cr]) * sc + beta[cr];
#pragma unroll
        for (int j = 0; j < 4; j++) {
            F2U v; v.u = acc[i][j];
            Rs[cr][2 * tx + 32 * j]     = fmaxf(v.f.x * sc + off, 0.f);
            Rs[cr][2 * tx + 32 * j + 1] = fmaxf(v.f.y * sc + off, 0.f);
        }
    }
    __syncthreads();

    if (t < SPAN) {
        const int co = t;
        unsigned long long wp[CRED];
        const float* wsp = w_span + co * CRED;
#pragma unroll
        for (int k = 0; k < CRED; k++) wp[k] = pack2(__ldg(wsp + k));
        const float bs = b_span[co];
        float* wout = g_wgt + ((size_t)bb * SPAN + co) * PLO + p0;

        for (int p4 = 0; p4 < 128; p4 += 4) {
            unsigned long long a0 = pack2(bs), a1 = pack2(bs);
#pragma unroll
            for (int k = 0; k < CRED; k++) {
                ulonglong2 rv = *(const ulonglong2*)&Rs[k][p4];
                a0 = fma2(wp[k], rv.x, a0);
                a1 = fma2(wp[k], rv.y, a1);
            }
            F2U u0, u1; u0.u = a0; u1.u = a1;
            *(float4*)&wout[p4] = make_float4(u0.f.x, u0.f.y, u1.f.x, u1.f.y);
        }
    }
}

// =====================================================================
// K3: involution (measured R3 version).
// =====================================================================
__global__ __launch_bounds__(256, 2)
void k3_involution(float* __restrict__ outp) {
    __shared__ float Hs[16 * 336];
    __shared__ float Wg[KK * 256];

    const int tile = blockIdx.x;
    const int g    = blockIdx.y;
    const int bb   = blockIdx.z;
    const int m0   = (tile >> 2) * 16;
    const int n0   = (tile & 3) * 16;
    const int t    = threadIdx.x;

    for (int idx = t; idx < 16 * 324; idx += 256) {
        int c  = idx / 324;
        int r2 = idx - c * 324;
        int mm = r2 / 18;
        int nn = r2 - mm * 18;
        int gm = m0 + mm - 1;
        int gn = n0 + nn - 1;
        float v = 0.f;
        if (gm >= 0 && gm < HLO && gn >= 0 && gn < WLO)
            v = g_h0[((size_t)(bb * COUT + g * GC_ + c)) * PLO + gm * WLO + gn];
        Hs[c * 336 + mm * 18 + nn] = v;
    }
    for (int idx = t; idx < KK * 256; idx += 256) {
        int k  = idx >> 8;
        int pp = idx & 255;
        int ml = pp >> 4;
        int nl = pp & 15;
        Wg[idx] = g_wgt[((size_t)(bb * SPAN + g * KK + k)) * PLO + (m0 + ml) * WLO + (n0 + nl)];
    }
    __syncthreads();

    const int c  = t >> 4;
    const int nl = t & 15;
    const int xg = (n0 + nl) * 2;

    for (int ml = 0; ml < 16; ml++) {
        float wv[KK];
#pragma unroll
        for (int k = 0; k < KK; k++) wv[k] = Wg[k * 256 + ml * 16 + nl];
        float hv[9];
#pragma unroll
        for (int dr = 0; dr < 3; dr++)
#pragma unroll
            for (int dc = 0; dc < 3; dc++)
                hv[dr * 3 + dc] = Hs[c * 336 + (ml + dr) * 18 + (nl + dc)];

        float a00 = 0.f, a01 = 0.f, a10 = 0.f, a11 = 0.f;
#pragma unroll
        for (int kh = 0; kh < 5; kh++) {
#pragma unroll
            for (int kw = 0; kw < 5; kw++) {
                const float w = wv[kh * 5 + kw];
                const int r0 = ((kh - 2) >> 1) + 1;
                const int r1 = ((kh - 1) >> 1) + 1;
                const int c0 = ((kw - 2) >> 1) + 1;
                const int c1 = ((kw - 1) >> 1) + 1;
                a00 = fmaf(w, hv[r0 * 3 + c0], a00);
                a01 = fmaf(w, hv[r0 * 3 + c1], a01);
                a10 = fmaf(w, hv[r1 * 3 + c0], a10);
                a11 = fmaf(w, hv[r1 * 3 + c1], a11);
            }
        }
        const int yb = (m0 + ml) * 2;
        size_t ob = ((size_t)(bb * COUT + g * GC_ + c) * HF + yb) * WF + xg;
        *(float2*)&outp[ob]      = make_float2(a00, a01);
        *(float2*)&outp[ob + WF] = make_float2(a10, a11);
    }
}

// =====================================================================
extern "C" void kernel_launch(void* const* d_in, const int* in_sizes, int n_in,
                              void* d_out, int out_size) {
    const float* x      = (const float*)d_in[0];
    const float* w1x1   = (const float*)d_in[1];
    const float* b1x1   = (const float*)d_in[2];
    const float* w_red  = (const float*)d_in[3];
    const float* b_red  = (const float*)d_in[4];
    const float* gamma  = (const float*)d_in[5];
    const float* beta   = (const float*)d_in[6];
    const float* mean   = (const float*)d_in[7];
    const float* var    = (const float*)d_in[8];
    const float* w_span = (const float*)d_in[9];
    const float* b_span = (const float*)d_in[10];
    float* out = (float*)d_out;

    cudaFuncSetAttribute(k1_mma, cudaFuncAttributeMaxDynamicSharedMemorySize, SM_TOT);

    k0_wsplit   <<<COUT * CIN / 2 / 256, 256>>>(w1x1);
    k1_mma      <<<dim3(PLO / TN, B_), 256, SM_TOT>>>(x, b1x1);
    k2_kernelgen<<<dim3(PLO / 128, B_), 256>>>(w_red, b_red, gamma, beta, mean, var,
                                               w_span, b_span);
    k3_involution<<<dim3(16, GROUPS, B_), 256>>>(out);
}